// round 16
// baseline (speedup 1.0000x reference)
#include <cuda_runtime.h>
#include <cuda_bf16.h>
#include <stdint.h>
#include <math.h>
#include <float.h>

#define Nn 50000
#define Ee 600000
#define Hh 128
#define Gg 512
#define PI_F 3.14159265358979323846f

// ---------------- scratch (device globals: no allocation allowed) ----------------
static __device__ float g_loop[(size_t)Nn * Hh];
static __device__ float g_xl[(size_t)Nn * Hh];
static __device__ float g_xr[(size_t)Nn * Hh];
static __device__ float g_ecsr[Ee];
static __device__ float g_eself[Nn];
static __device__ float g_agg[(size_t)Nn * Hh];
static __device__ float g_h[(size_t)Nn * Hh];
static __device__ float g_gate[(size_t)Nn * Hh];
static __device__ float g_tmp[(size_t)Nn * Hh];
static __device__ float g_bnsum[Hh];
static __device__ float g_bnsq[Hh];
static __device__ float g_mu[Hh];
static __device__ float g_inv[Hh];
static __device__ float g_pooled[Gg * Hh];
static __device__ int g_rowptr[Nn + 1];
static __device__ int g_wp[Nn];
static __device__ int g_bsum[256];
static __device__ int g_eid[Ee];
static __device__ int g_srcC[Ee];
static __device__ int g_pos[Ee];
static __device__ int g_gstart[Gg + 1];
#define BLOB_BYTES 69632
static __device__ __align__(16) unsigned char g_bw[9 * BLOB_BYTES];

// ---------------- mma.sync / cp.async helpers ----------------
__device__ __forceinline__ void ldm_x4(uint32_t r[4], uint32_t addr) {
    asm volatile("ldmatrix.sync.aligned.m8n8.x4.shared.b16 {%0,%1,%2,%3}, [%4];"
                 : "=r"(r[0]), "=r"(r[1]), "=r"(r[2]), "=r"(r[3]) : "r"(addr));
}

__device__ __forceinline__ void mma16816(float* c, const uint32_t a[4], uint32_t b0, uint32_t b1) {
    asm volatile(
        "mma.sync.aligned.m16n8k16.row.col.f32.bf16.bf16.f32 "
        "{%0,%1,%2,%3}, {%4,%5,%6,%7}, {%8,%9}, {%0,%1,%2,%3};"
        : "+f"(c[0]), "+f"(c[1]), "+f"(c[2]), "+f"(c[3])
        : "r"(a[0]), "r"(a[1]), "r"(a[2]), "r"(a[3]), "r"(b0), "r"(b1));
}

#define CP_ASYNC16(saddr, gptr) \
    asm volatile("cp.async.cg.shared.global [%0], [%1], 16;" \
                 :: "r"((uint32_t)(saddr)), "l"(gptr) : "memory")
#define CP_COMMIT() asm volatile("cp.async.commit_group;" ::: "memory")
#define CP_WAIT0() asm volatile("cp.async.wait_group 0;" ::: "memory")

#define ROWSTRIDE 272  // 136 bf16 * 2B

// ---- 16x64 warp-tile mainloop: c[32] = [np(4)][f(2)][4]
__device__ __forceinline__ void mm16x64(float* c, uint32_t aHi, uint32_t aLo,
                                        uint32_t bHi, uint32_t bLo) {
#pragma unroll
    for (int ks = 0; ks < 8; ks++) {
        uint32_t ahi[4], alo[4];
        ldm_x4(ahi, aHi + ks * 32);
        ldm_x4(alo, aLo + ks * 32);
#pragma unroll
        for (int np = 0; np < 4; np++) {
            uint32_t bh[4], bl[4];
            ldm_x4(bh, bHi + np * (16 * ROWSTRIDE) + ks * 32);
            ldm_x4(bl, bLo + np * (16 * ROWSTRIDE) + ks * 32);
            float* c0 = c + 8 * np;
            float* c1 = c + 8 * np + 4;
            mma16816(c0, ahi, bh[0], bh[1]);
            mma16816(c1, ahi, bh[2], bh[3]);
            mma16816(c0, ahi, bl[0], bl[1]);
            mma16816(c1, ahi, bl[2], bl[3]);
            mma16816(c0, alo, bh[0], bh[1]);
            mma16816(c1, alo, bh[2], bh[3]);
        }
    }
}

__device__ __forceinline__ void cvt_sts(unsigned char* smem, uint32_t hiBase, uint32_t loBase,
                                        uint32_t off, float4 v) {
    __nv_bfloat162 h01 = __floats2bfloat162_rn(v.x, v.y);
    __nv_bfloat162 h23 = __floats2bfloat162_rn(v.z, v.w);
    __nv_bfloat162 l01 = __floats2bfloat162_rn(v.x - __low2float(h01), v.y - __high2float(h01));
    __nv_bfloat162 l23 = __floats2bfloat162_rn(v.z - __low2float(h23), v.w - __high2float(h23));
    *reinterpret_cast<uint2*>(smem + hiBase + off) =
        make_uint2(*reinterpret_cast<uint32_t*>(&h01), *reinterpret_cast<uint32_t*>(&h23));
    *reinterpret_cast<uint2*>(smem + loBase + off) =
        make_uint2(*reinterpret_cast<uint32_t*>(&l01), *reinterpret_cast<uint32_t*>(&l23));
}

__global__ void k_fill(float* __restrict__ p, float v, int n) {
    int i = blockIdx.x * blockDim.x + threadIdx.x;
    if (i < n) p[i] = v;
}

__global__ void k_ifill(int* __restrict__ p, int v, int n) {
    int i = blockIdx.x * blockDim.x + threadIdx.x;
    if (i < n) p[i] = v;
}

// ---------------- CSR build (hierarchical scan) ----------------
__global__ void k_hist(const int* __restrict__ ei) {
    int e = blockIdx.x * blockDim.x + threadIdx.x;
    if (e < Ee) atomicAdd(&g_wp[ei[Ee + e]], 1);
}

__global__ void k_scanA() {
    __shared__ int sh[256];
    int b = blockIdx.x, t = threadIdx.x;
    int i = b * 256 + t;
    int v = (i < Nn) ? g_wp[i] : 0;
    sh[t] = v;
    __syncthreads();
#pragma unroll
    for (int o = 1; o < 256; o <<= 1) {
        int u = (t >= o) ? sh[t - o] : 0;
        __syncthreads();
        sh[t] += u;
        __syncthreads();
    }
    if (i < Nn) g_rowptr[i] = sh[t] - v;
    if (t == 255) g_bsum[b] = sh[255];
}

__global__ void k_scanB(int nblk) {
    __shared__ int sh[256];
    int t = threadIdx.x;
    int v = (t < nblk) ? g_bsum[t] : 0;
    sh[t] = v;
    __syncthreads();
#pragma unroll
    for (int o = 1; o < 256; o <<= 1) {
        int u = (t >= o) ? sh[t - o] : 0;
        __syncthreads();
        sh[t] += u;
        __syncthreads();
    }
    if (t < nblk) g_bsum[t] = sh[t] - v;
}

__global__ void k_scanC() {
    int i = blockIdx.x * blockDim.x + threadIdx.x;
    if (i < Nn) {
        int v = g_rowptr[i] + g_bsum[i >> 8];
        g_rowptr[i] = v;
        g_wp[i] = v;
    }
    if (i == 0) g_rowptr[Nn] = Ee;
}

__global__ void k_place(const int* __restrict__ ei) {
    int e = blockIdx.x * blockDim.x + threadIdx.x;
    if (e >= Ee) return;
    int d = ei[Ee + e];
    int p = atomicAdd(&g_wp[d], 1);
    g_pos[e] = p;
    g_eid[p] = e;
    g_srcC[p] = ei[e];
}

// ---------------- loop_attr mean (CSR gather) ----------------
__global__ void k_loop_mean(const float* __restrict__ eattr) {
    int t = blockIdx.x * blockDim.x + threadIdx.x;
    int d = t >> 5, lane = t & 31;
    if (d >= Nn) return;
    int start = g_rowptr[d], end = g_rowptr[d + 1];
    float4 acc = make_float4(0.f, 0.f, 0.f, 0.f);
    for (int j = start; j < end; j++) {
        int eid = g_eid[j];
        float4 a = reinterpret_cast<const float4*>(eattr)[(size_t)eid * 32 + lane];
        acc.x += a.x; acc.y += a.y; acc.z += a.z; acc.w += a.w;
    }
    float inv = 1.f / (float)max(end - start, 1);
    reinterpret_cast<float4*>(g_loop)[(size_t)d * 32 + lane] =
        make_float4(acc.x * inv, acc.y * inv, acc.z * inv, acc.w * inv);
}

// ---------------- per-dst softmax + aggregation, fused BN stats ----------------
// grid: 6250 blocks x 256 threads (8 nodes/block; Nn = 50000 = 6250*8 exactly)
__global__ void k_node_agg() {
    __shared__ float sb_s[128];
    __shared__ float sb_q[128];
    int t = blockIdx.x * blockDim.x + threadIdx.x;
    int d = t >> 5, lane = threadIdx.x & 31;
    bool active = d < Nn;

    if (threadIdx.x < 128) { sb_s[threadIdx.x] = 0.f; sb_q[threadIdx.x] = 0.f; }
    __syncthreads();

    float4 acc = make_float4(0.f, 0.f, 0.f, 0.f);
    if (active) {
        int start = g_rowptr[d], end = g_rowptr[d + 1];
        float es = g_eself[d];
        float m = es;
        for (int j = start + lane; j < end; j += 32) m = fmaxf(m, g_ecsr[j]);
#pragma unroll
        for (int o = 16; o > 0; o >>= 1) m = fmaxf(m, __shfl_xor_sync(0xffffffffu, m, o));
        float s = (lane == 0) ? __expf(es - m) : 0.f;
        for (int j = start + lane; j < end; j += 32) s += __expf(g_ecsr[j] - m);
#pragma unroll
        for (int o = 16; o > 0; o >>= 1) s += __shfl_xor_sync(0xffffffffu, s, o);
        float inv = 1.f / s;
        float aS = __expf(es - m) * inv;
        float4 xv = reinterpret_cast<const float4*>(g_xl)[(size_t)d * 32 + lane];
        acc = make_float4(aS * xv.x, aS * xv.y, aS * xv.z, aS * xv.w);
        for (int j = start; j < end; j++) {
            float a = __expf(g_ecsr[j] - m) * inv;
            int sn = g_srcC[j];
            float4 v = reinterpret_cast<const float4*>(g_xl)[(size_t)sn * 32 + lane];
            acc.x = fmaf(a, v.x, acc.x); acc.y = fmaf(a, v.y, acc.y);
            acc.z = fmaf(a, v.z, acc.z); acc.w = fmaf(a, v.w, acc.w);
        }
        reinterpret_cast<float4*>(g_agg)[(size_t)d * 32 + lane] = acc;
        // block-local BN stats (BN is shift-invariant so cb cancels; stats on raw acc)
        int c0 = lane * 4;
        atomicAdd(&sb_s[c0 + 0], acc.x); atomicAdd(&sb_q[c0 + 0], acc.x * acc.x);
        atomicAdd(&sb_s[c0 + 1], acc.y); atomicAdd(&sb_q[c0 + 1], acc.y * acc.y);
        atomicAdd(&sb_s[c0 + 2], acc.z); atomicAdd(&sb_q[c0 + 2], acc.z * acc.z);
        atomicAdd(&sb_s[c0 + 3], acc.w); atomicAdd(&sb_q[c0 + 3], acc.w * acc.w);
    }
    __syncthreads();
    if (threadIdx.x < 128) {
        atomicAdd(&g_bnsum[threadIdx.x], sb_s[threadIdx.x]);
        atomicAdd(&g_bnsq[threadIdx.x], sb_q[threadIdx.x]);
    }
}

// ---------------- weight pre-split ----------------
struct W9 { const float* p[9]; };

__global__ void k_prep_all(W9 w, unsigned char* __restrict__ bw) {
    int idx = blockIdx.x * blockDim.x + threadIdx.x;
    if (idx >= 9 * 16384) return;
    int mi = idx >> 14;
    int rem = idx & 16383;
    int n = rem >> 7;
    int k = rem & 127;
    const float* W = w.p[mi];
    unsigned char* blob = bw + (size_t)mi * BLOB_BYTES;
    float v = W[k * 128 + n];
    __nv_bfloat16 h = __float2bfloat16_rn(v);
    __nv_bfloat16 l = __float2bfloat16_rn(v - __bfloat162float(h));
    size_t off = ((size_t)n * 136 + k) * 2;
    *reinterpret_cast<unsigned short*>(blob + off) = *reinterpret_cast<unsigned short*>(&h);
    *reinterpret_cast<unsigned short*>(blob + 34816 + off) = *reinterpret_cast<unsigned short*>(&l);
}

#define SM_ATT 0
#define SM_RED 512
#define SM_A_HI 1024
#define SM_A_LO 35840
#define SM_B_HI 70656
#define SMEM_BYTES 140288

// ===================== persistent edge+self score GEMM =====================
__global__ void __launch_bounds__(512, 1)
k_edge_persist(const float* __restrict__ eattr, const unsigned char* __restrict__ Bblob,
               const float* __restrict__ att, const int* __restrict__ ei,
               const float* __restrict__ xl, const float* __restrict__ xr,
               int tilesE, int tilesT) {
    extern __shared__ unsigned char smem[];
    const int tid = threadIdx.x;
    const int wid = tid >> 5;
    const int lane = tid & 31;
    const int rowtile = wid & 7;
    const int colhalf = wid >> 3;
    uint32_t sb;
    asm("{ .reg .u64 t; cvta.to.shared.u64 t, %1; cvt.u32.u64 %0, t; }" : "=r"(sb) : "l"(smem));

#pragma unroll
    for (int i = 0; i < 9; i++) {
        int idx = tid + 512 * i;
        if (idx < 4352) CP_ASYNC16(sb + SM_B_HI + idx * 16, Bblob + (size_t)idx * 16);
    }
    CP_COMMIT();
    if (tid < 32)
        reinterpret_cast<float4*>(smem + SM_ATT)[tid] = reinterpret_cast<const float4*>(att)[tid];
    CP_WAIT0();
    __syncthreads();

    const float* att_s = reinterpret_cast<const float*>(smem + SM_ATT);
    float* sred = reinterpret_cast<float*>(smem + SM_RED);

    uint32_t a_off = (uint32_t)(rowtile * 16 + (lane & 7) + ((lane >> 3) & 1) * 8) * ROWSTRIDE
                     + ((lane >> 4) & 1) * 16;
    uint32_t b_off = (uint32_t)(colhalf * 64 + (lane & 7) + ((lane >> 4) & 1) * 8) * ROWSTRIDE
                     + ((lane >> 3) & 1) * 16;
    uint32_t aHi = sb + SM_A_HI + a_off;
    uint32_t aLo = sb + SM_A_LO + a_off;
    uint32_t bHi = sb + SM_B_HI + b_off;
    uint32_t bLo = bHi + 34816;
    const int q = lane & 3;

    for (int tile = blockIdx.x; tile < tilesT; tile += gridDim.x) {
        const bool selfmode = tile >= tilesE;
        const int row0 = (selfmode ? tile - tilesE : tile) * 128;
        const int limit = selfmode ? Nn : Ee;
        const float* Asrc = selfmode ? g_loop : eattr;

#pragma unroll
        for (int i = 0; i < 8; i++) {
            int idx = tid + 512 * i;
            int r = idx >> 5;
            int c4 = (idx & 31) << 2;
            int grow = row0 + r;
            float4 v = make_float4(0.f, 0.f, 0.f, 0.f);
            if (grow < limit)
                v = *reinterpret_cast<const float4*>(Asrc + (size_t)grow * Hh + c4);
            cvt_sts(smem, SM_A_HI, SM_A_LO, (uint32_t)r * ROWSTRIDE + c4 * 2, v);
        }
        __syncthreads();

        float c[32];
#pragma unroll
        for (int i = 0; i < 32; i++) c[i] = 0.f;

        mm16x64(c, aHi, aLo, bHi, bLo);

        const int r1 = row0 + rowtile * 16 + (lane >> 2);
        float accv[2];
        int rowv[2];
#pragma unroll
        for (int p = 0; p < 2; p++) {
            int row = r1 + 8 * p;
            rowv[p] = row;
            bool valid = row < limit;
            int s = 0, dd = 0;
            if (valid) {
                if (selfmode) { s = row; dd = row; }
                else { s = ei[row]; dd = ei[Ee + row]; }
            }
            const float* xlp = xl + (size_t)s * Hh;
            const float* xrp = xr + (size_t)dd * Hh;
            float acc = 0.f;
            if (valid) {
#pragma unroll
                for (int j = 0; j < 8; j++) {
                    int col = colhalf * 64 + j * 8 + q * 2;
                    int base = 8 * (j >> 1) + 4 * (j & 1) + 2 * p;
                    float2 xa = *reinterpret_cast<const float2*>(xlp + col);
                    float2 xb = *reinterpret_cast<const float2*>(xrp + col);
                    float2 at = *reinterpret_cast<const float2*>(att_s + col);
                    float m;
                    m = c[base + 0] + xa.x + xb.x;
                    m = m > 0.f ? m : 0.2f * m;
                    acc = fmaf(m, at.x, acc);
                    m = c[base + 1] + xa.y + xb.y;
                    m = m > 0.f ? m : 0.2f * m;
                    acc = fmaf(m, at.y, acc);
                }
            }
            acc += __shfl_xor_sync(0xffffffffu, acc, 1);
            acc += __shfl_xor_sync(0xffffffffu, acc, 2);
            accv[p] = acc;
        }
        int rl = rowtile * 16 + (lane >> 2);
        if (colhalf == 0 && q == 0) {
            sred[rl] = accv[0];
            sred[rl + 8] = accv[1];
        }
        __syncthreads();
        if (colhalf == 1 && q == 0) {
#pragma unroll
            for (int p = 0; p < 2; p++) {
                if (rowv[p] < limit) {
                    float e = accv[p] + sred[rl + 8 * p];
                    if (selfmode) g_eself[rowv[p]] = e;
                    else g_ecsr[g_pos[rowv[p]]] = e;
                }
            }
        }
        __syncthreads();
    }
}

// ===================== persistent BM=128 GEMM, 512 threads (gate/final) =====================
// EPI: 0 store+bias, 1 tanh(+bias), 2 tanh(+bias)*PI
template <int EPI>
__global__ void __launch_bounds__(512, 1)
k_mma_pers(const float* __restrict__ A, const unsigned char* __restrict__ Bblob,
           const float* __restrict__ bias, float* __restrict__ C, int rows, int tilesT) {
    extern __shared__ unsigned char smem[];
    const int tid = threadIdx.x;
    const int wid = tid >> 5;
    const int lane = tid & 31;
    const int rowtile = wid & 7;
    const int colhalf = wid >> 3;
    uint32_t sb;
    asm("{ .reg .u64 t; cvta.to.shared.u64 t, %1; cvt.u32.u64 %0, t; }" : "=r"(sb) : "l"(smem));

#pragma unroll
    for (int i = 0; i < 9; i++) {
        int idx = tid + 512 * i;
        if (idx < 4352) CP_ASYNC16(sb + SM_B_HI + idx * 16, Bblob + (size_t)idx * 16);
    }
    CP_COMMIT();
    CP_WAIT0();
    __syncthreads();

    uint32_t a_off = (uint32_t)(rowtile * 16 + (lane & 7) + ((lane >> 3) & 1) * 8) * ROWSTRIDE
                     + ((lane >> 4) & 1) * 16;
    uint32_t b_off = (uint32_t)(colhalf * 64 + (lane & 7) + ((lane >> 4) & 1) * 8) * ROWSTRIDE
                     + ((lane >> 3) & 1) * 16;
    uint32_t aHi = sb + SM_A_HI + a_off;
    uint32_t aLo = sb + SM_A_LO + a_off;
    uint32_t bHi = sb + SM_B_HI + b_off;
    uint32_t bLo = bHi + 34816;
    const int q = lane & 3;

    for (int tile = blockIdx.x; tile < tilesT; tile += gridDim.x) {
        const int row0 = tile * 128;
#pragma unroll
        for (int i = 0; i < 8; i++) {
            int idx = tid + 512 * i;
            int r = idx >> 5;
            int c4 = (idx & 31) << 2;
            int grow = row0 + r;
            float4 v = make_float4(0.f, 0.f, 0.f, 0.f);
            if (grow < rows)
                v = *reinterpret_cast<const float4*>(A + (size_t)grow * Hh + c4);
            cvt_sts(smem, SM_A_HI, SM_A_LO, (uint32_t)r * ROWSTRIDE + c4 * 2, v);
        }
        __syncthreads();

        float c[32];
#pragma unroll
        for (int i = 0; i < 32; i++) c[i] = 0.f;

        mm16x64(c, aHi, aLo, bHi, bLo);

        const int r1 = row0 + rowtile * 16 + (lane >> 2);
        int r2 = r1 + 8;
#pragma unroll
        for (int j = 0; j < 8; j++) {
            int col = colhalf * 64 + j * 8 + q * 2;
            int base = 8 * (j >> 1) + 4 * (j & 1);
            float b0 = bias[col], b1 = bias[col + 1];
            if (r1 < rows) {
                float ox = c[base + 0] + b0;
                float oy = c[base + 1] + b1;
                if (EPI == 1) { ox = tanhf(ox); oy = tanhf(oy); }
                if (EPI == 2) { ox = tanhf(ox) * PI_F; oy = tanhf(oy) * PI_F; }
                *reinterpret_cast<float2*>(C + (size_t)r1 * Hh + col) = make_float2(ox, oy);
            }
            if (r2 < rows) {
                float ox = c[base + 2] + b0;
                float oy = c[base + 3] + b1;
                if (EPI == 1) { ox = tanhf(ox); oy = tanhf(oy); }
                if (EPI == 2) { ox = tanhf(ox) * PI_F; oy = tanhf(oy) * PI_F; }
                *reinterpret_cast<float2*>(C + (size_t)r2 * Hh + col) = make_float2(ox, oy);
            }
        }
        __syncthreads();
    }
}

// ===================== persistent dual-B BM=64 GEMM =====================
#define SD_A_HI 0
#define SD_A_LO 17408
#define SD_B 34816
#define SMEM_DUAL 174080

__global__ void __launch_bounds__(512, 1)
k_gemm_dual(const float* __restrict__ A,
            const unsigned char* __restrict__ B1, const unsigned char* __restrict__ B2,
            const float* __restrict__ bias1, const float* __restrict__ bias2,
            float* __restrict__ C1, float* __restrict__ C2, int rows, int tilesT) {
    extern __shared__ unsigned char smem[];
    const int tid = threadIdx.x;
    const int wid = tid >> 5;
    const int lane = tid & 31;
    const int rowtile = wid & 3;
    const int colhalf = (wid >> 2) & 1;
    const int outsel = wid >> 3;
    uint32_t sb;
    asm("{ .reg .u64 t; cvta.to.shared.u64 t, %1; cvt.u32.u64 %0, t; }" : "=r"(sb) : "l"(smem));

#pragma unroll
    for (int i = 0; i < 9; i++) {
        int idx = tid + 512 * i;
        if (idx < 4352) {
            CP_ASYNC16(sb + SD_B + idx * 16, B1 + (size_t)idx * 16);
            CP_ASYNC16(sb + SD_B + BLOB_BYTES + idx * 16, B2 + (size_t)idx * 16);
        }
    }
    CP_COMMIT();
    CP_WAIT0();
    __syncthreads();

    uint32_t a_off = (uint32_t)(rowtile * 16 + (lane & 7) + ((lane >> 3) & 1) * 8) * ROWSTRIDE
                     + ((lane >> 4) & 1) * 16;
    uint32_t b_off = (uint32_t)(colhalf * 64 + (lane & 7) + ((lane >> 4) & 1) * 8) * ROWSTRIDE
                     + ((lane >> 3) & 1) * 16;
    uint32_t aHi = sb + SD_A_HI + a_off;
    uint32_t aLo = sb + SD_A_LO + a_off;
    uint32_t bHi = sb + SD_B + outsel * BLOB_BYTES + b_off;
    uint32_t bLo = bHi + 34816;
    const int q = lane & 3;
    const float* bias = outsel ? bias2 : bias1;
    float* C = outsel ? C2 : C1;

    for (int tile = blockIdx.x; tile < tilesT; tile += gridDim.x) {
        const int row0 = tile * 64;
#pragma unroll
        for (int i = 0; i < 4; i++) {
            int idx = tid + 512 * i;
            int r = idx >> 5;
            int c4 = (idx & 31) << 2;
            int grow = row0 + r;
            float4 v = make_float4(0.f, 0.f, 0.f, 0.f);
            if (grow < rows)
                v = *reinterpret_cast<const float4*>(A + (size_t)grow * Hh + c4);
            cvt_sts(smem, SD_A_HI, SD_A_LO, (uint32_t)r * ROWSTRIDE + c4 * 2, v);
        }
        __syncthreads();

        float c[32];
#pragma unroll
        for (int i = 0; i < 32; i++) c[i] = 0.f;

        mm16x64(c, aHi, aLo, bHi, bLo);

        const int r1 = row0 + rowtile * 16 + (lane >> 2);
        const int r2 = r1 + 8;
#pragma unroll
        for (int j = 0; j < 8; j++) {
            int col = colhalf * 64 + j * 8 + q * 2;
            int base = 8 * (j >> 1) + 4 * (j & 1);
            float b0 = bias[col], b1 = bias[col + 1];
            if (r1 < rows)
                *reinterpret_cast<float2*>(C + (size_t)r1 * Hh + col) =
                    make_float2(c[base + 0] + b0, c[base + 1] + b1);
            if (r2 < rows)
                *reinterpret_cast<float2*>(C + (size_t)r2 * Hh + col) =
                    make_float2(c[base + 2] + b0, c[base + 3] + b1);
        }
        __syncthreads();
    }
}

// ---------------- batchnorm finalize + apply ----------------
__global__ void k_bn_final() {
    int j = threadIdx.x;
    float mu = g_bnsum[j] / (float)Nn;
    float var = g_bnsq[j] / (float)Nn - mu * mu;
    g_mu[j] = mu;
    g_inv[j] = rsqrtf(var + 1e-5f);
    g_bnsum[j] = 0.f;
    g_bnsq[j] = 0.f;
}

__global__ void k_bn_apply(const float* __restrict__ gam, const float* __restrict__ bet) {
    int i = blockIdx.x * blockDim.x + threadIdx.x;
    if (i >= Nn * Hh) return;
    int j = i & 127;
    float v = (g_agg[i] - g_mu[j]) * g_inv[j] * gam[j] + bet[j];
    g_h[i] = tanhf(v);
}

// ---------------- pooling over sorted batch segments ----------------
__global__ void k_gb_min(const int* __restrict__ batch) {
    int n = blockIdx.x * blockDim.x + threadIdx.x;
    if (n < Nn) atomicMin(&g_gstart[batch[n]], n);
}

__global__ void k_gb_fix() {
    __shared__ int sh[Gg];
    int t = threadIdx.x;
    sh[t] = g_gstart[t];
    __syncthreads();
#pragma unroll
    for (int o = 1; o < Gg; o <<= 1) {
        int u = (t + o < Gg) ? sh[t + o] : Nn;
        __syncthreads();
        sh[t] = min(sh[t], u);
        __syncthreads();
    }
    g_gstart[t] = sh[t];
    if (t == 0) g_gstart[Gg] = Nn;
}

__global__ void k_pool() {
    int g = blockIdx.x;
    int j = threadIdx.x;
    int s = g_gstart[g], e2 = g_gstart[g + 1];
    float m = -FLT_MAX;
    for (int n = s; n < e2; n++) m = fmaxf(m, g_gate[(size_t)n * Hh + j]);
    float den = 0.f, num = 0.f;
    for (int n = s; n < e2; n++) {
        float ex = __expf(g_gate[(size_t)n * Hh + j] - m);
        den += ex;
        num = fmaf(ex, g_h[(size_t)n * Hh + j], num);
    }
    g_pooled[g * Hh + j] = num / fmaxf(den, 1e-16f);
}

// ---------------- launch ----------------
static inline int cdiv(long a, long b) { return (int)((a + b - 1) / b); }

extern "C" void kernel_launch(void* const* d_in, const int* in_sizes, int n_in,
                              void* d_out, int out_size) {
    const float* x     = (const float*)d_in[0];
    const int*   ei    = (const int*)d_in[1];
    const float* eattr = (const float*)d_in[2];
    const int*   batch = (const int*)d_in[3];
    const float* Wl[2]  = {(const float*)d_in[4],  (const float*)d_in[11]};
    const float* bl[2]  = {(const float*)d_in[5],  (const float*)d_in[12]};
    const float* Wr[2]  = {(const float*)d_in[6],  (const float*)d_in[13]};
    const float* br[2]  = {(const float*)d_in[7],  (const float*)d_in[14]};
    const float* We[2]  = {(const float*)d_in[8],  (const float*)d_in[15]};
    const float* att[2] = {(const float*)d_in[9],  (const float*)d_in[16]};
    const float* cb[2]  = {(const float*)d_in[10], (const float*)d_in[17]};  // cancels in BN
    const float* gm[2]  = {(const float*)d_in[18], (const float*)d_in[20]};
    const float* bt[2]  = {(const float*)d_in[19], (const float*)d_in[21]};
    const float* A1 = (const float*)d_in[22]; const float* a1 = (const float*)d_in[23];
    const float* A2 = (const float*)d_in[24]; const float* a2 = (const float*)d_in[25];
    const float* Wf = (const float*)d_in[26]; const float* bf = (const float*)d_in[27];
    float* out = (float*)d_out;
    (void)cb;

    float *p_xl, *p_xr, *p_h, *p_gate, *p_tmp, *p_pooled;
    int *p_wp, *p_gstart;
    unsigned char* p_bw;
    cudaGetSymbolAddress((void**)&p_xl, g_xl);
    cudaGetSymbolAddress((void**)&p_xr, g_xr);
    cudaGetSymbolAddress((void**)&p_h, g_h);
    cudaGetSymbolAddress((void**)&p_gate, g_gate);
    cudaGetSymbolAddress((void**)&p_tmp, g_tmp);
    cudaGetSymbolAddress((void**)&p_pooled, g_pooled);
    cudaGetSymbolAddress((void**)&p_wp, g_wp);
    cudaGetSymbolAddress((void**)&p_gstart, g_gstart);
    cudaGetSymbolAddress((void**)&p_bw, g_bw);

    cudaFuncSetAttribute(k_mma_pers<0>, cudaFuncAttributeMaxDynamicSharedMemorySize, SMEM_BYTES);
    cudaFuncSetAttribute(k_mma_pers<1>, cudaFuncAttributeMaxDynamicSharedMemorySize, SMEM_BYTES);
    cudaFuncSetAttribute(k_mma_pers<2>, cudaFuncAttributeMaxDynamicSharedMemorySize, SMEM_BYTES);
    cudaFuncSetAttribute(k_edge_persist, cudaFuncAttributeMaxDynamicSharedMemorySize, SMEM_BYTES);
    cudaFuncSetAttribute(k_gemm_dual, cudaFuncAttributeMaxDynamicSharedMemorySize, SMEM_DUAL);

    const int NH = Nn * Hh;
    const int tilesN = cdiv(Nn, 128), tilesE = cdiv(Ee, 128), tilesG = cdiv(Gg, 128);
    const int t64N = cdiv(Nn, 64);
    const int nScanBlk = cdiv(Nn, 256);
    const int gN = tilesN < 148 ? tilesN : 148;

    // 0: weight blobs (order: Wl1,Wr1,We1,Wl2,Wr2,We2,A1,A2,Wf)
    W9 w9;
    w9.p[0] = Wl[0]; w9.p[1] = Wr[0]; w9.p[2] = We[0];
    w9.p[3] = Wl[1]; w9.p[4] = Wr[1]; w9.p[5] = We[1];
    w9.p[6] = A1; w9.p[7] = A2; w9.p[8] = Wf;
    k_prep_all<<<cdiv(9 * 16384, 512), 512>>>(w9, p_bw);

    // 1-2: CSR histogram
    k_ifill<<<cdiv(Nn, 256), 256>>>(p_wp, 0, Nn);
    k_hist<<<cdiv(Ee, 256), 256>>>(ei);

    // 3: layer-1 xl/xr persistent dual GEMM (ncu capture slot)
    k_gemm_dual<<<148, 512, SMEM_DUAL>>>(x, p_bw, p_bw + BLOB_BYTES, bl[0], br[0],
                                         p_xl, p_xr, Nn, t64N);

    // CSR scan + placement
    k_scanA<<<nScanBlk, 256>>>();
    k_scanB<<<1, 256>>>(nScanBlk);
    k_scanC<<<cdiv(Nn, 256), 256>>>();
    k_place<<<cdiv(Ee, 256), 256>>>(ei);

    // graph segment bounds + loop_attr mean
    k_ifill<<<cdiv(Gg + 1, 256), 256>>>(p_gstart, Nn, Gg + 1);
    k_gb_min<<<cdiv(Nn, 256), 256>>>(batch);
    k_gb_fix<<<1, Gg>>>();
    k_loop_mean<<<cdiv((long)Nn * 32, 256), 256>>>(eattr);

    for (int l = 0; l < 2; l++) {
        const unsigned char* bwe = p_bw + (size_t)(3 * l + 2) * BLOB_BYTES;
        if (l == 1) {
            k_gemm_dual<<<148, 512, SMEM_DUAL>>>(p_h, p_bw + 3ul * BLOB_BYTES,
                                                 p_bw + 4ul * BLOB_BYTES, bl[1], br[1],
                                                 p_xl, p_xr, Nn, t64N);
        }
        // persistent fused edge+self score GEMM
        k_edge_persist<<<148, 512, SMEM_BYTES>>>(eattr, bwe, att[l], ei,
                                                 p_xl, p_xr, tilesE, tilesE + tilesN);
        // aggregation with fused BN stats (cb cancels in BN)
        k_node_agg<<<cdiv((long)Nn * 32, 256), 256>>>();

        k_bn_final<<<1, 128>>>();
        k_bn_apply<<<cdiv(NH, 256), 256>>>(gm[l], bt[l]);
    }

    // gate = tanh(h@A1+a1)@A2 + a2  (persistent)
    k_mma_pers<1><<<gN, 512, SMEM_BYTES>>>(p_h, p_bw + 6ul * BLOB_BYTES, a1, p_tmp, Nn, tilesN);
    k_mma_pers<0><<<gN, 512, SMEM_BYTES>>>(p_tmp, p_bw + 7ul * BLOB_BYTES, a2, p_gate, Nn, tilesN);
    k_pool<<<Gg, 128>>>();

    // final linear + tanh*pi -> axis; aperture = zeros
    k_mma_pers<2><<<tilesG, 512, SMEM_BYTES>>>(p_pooled, p_bw + 8ul * BLOB_BYTES, bf, out, Gg, tilesG);
    int rem = out_size - Gg * Hh;
    if (rem > 0) k_fill<<<cdiv(rem, 256), 256>>>(out + Gg * Hh, 0.f, rem);
}

// round 17
// speedup vs baseline: 1.0269x; 1.0269x over previous
#include <cuda_runtime.h>
#include <cuda_bf16.h>
#include <stdint.h>
#include <math.h>
#include <float.h>

#define Nn 50000
#define Ee 600000
#define Hh 128
#define Gg 512
#define PI_F 3.14159265358979323846f

// ---------------- scratch (device globals: no allocation allowed) ----------------
static __device__ float g_loop[(size_t)Nn * Hh];
static __device__ float g_xl[(size_t)Nn * Hh];
static __device__ float g_xr[(size_t)Nn * Hh];
static __device__ float g_ecsr[Ee];
static __device__ float g_eself[Nn];
static __device__ float g_agg[(size_t)Nn * Hh];
static __device__ float g_h[(size_t)Nn * Hh];
static __device__ float g_gate[(size_t)Nn * Hh];
static __device__ float g_tmp[(size_t)Nn * Hh];
static __device__ float g_bnsum[Hh];
static __device__ float g_bnsq[Hh];
static __device__ float g_mu[Hh];
static __device__ float g_inv[Hh];
static __device__ float g_pooled[Gg * Hh];
static __device__ int g_rowptr[Nn + 1];
static __device__ int g_wp[Nn];
static __device__ int g_bsum[256];
static __device__ int g_eid[Ee];
static __device__ int g_srcC[Ee];
static __device__ int g_pos[Ee];
static __device__ int g_gstart[Gg + 1];
#define BLOB_BYTES 69632
static __device__ __align__(16) unsigned char g_bw[9 * BLOB_BYTES];

// ---------------- mma.sync / cp.async helpers ----------------
__device__ __forceinline__ void ldm_x4(uint32_t r[4], uint32_t addr) {
    asm volatile("ldmatrix.sync.aligned.m8n8.x4.shared.b16 {%0,%1,%2,%3}, [%4];"
                 : "=r"(r[0]), "=r"(r[1]), "=r"(r[2]), "=r"(r[3]) : "r"(addr));
}

__device__ __forceinline__ void mma16816(float* c, const uint32_t a[4], uint32_t b0, uint32_t b1) {
    asm volatile(
        "mma.sync.aligned.m16n8k16.row.col.f32.bf16.bf16.f32 "
        "{%0,%1,%2,%3}, {%4,%5,%6,%7}, {%8,%9}, {%0,%1,%2,%3};"
        : "+f"(c[0]), "+f"(c[1]), "+f"(c[2]), "+f"(c[3])
        : "r"(a[0]), "r"(a[1]), "r"(a[2]), "r"(a[3]), "r"(b0), "r"(b1));
}

#define CP_ASYNC16(saddr, gptr) \
    asm volatile("cp.async.cg.shared.global [%0], [%1], 16;" \
                 :: "r"((uint32_t)(saddr)), "l"(gptr) : "memory")
#define CP_COMMIT() asm volatile("cp.async.commit_group;" ::: "memory")
#define CP_WAIT0() asm volatile("cp.async.wait_group 0;" ::: "memory")

#define ROWSTRIDE 272  // 136 bf16 * 2B

// ---- 16x64 warp-tile mainloop: c[32] = [np(4)][f(2)][4]
__device__ __forceinline__ void mm16x64(float* c, uint32_t aHi, uint32_t aLo,
                                        uint32_t bHi, uint32_t bLo) {
#pragma unroll
    for (int ks = 0; ks < 8; ks++) {
        uint32_t ahi[4], alo[4];
        ldm_x4(ahi, aHi + ks * 32);
        ldm_x4(alo, aLo + ks * 32);
#pragma unroll
        for (int np = 0; np < 4; np++) {
            uint32_t bh[4], bl[4];
            ldm_x4(bh, bHi + np * (16 * ROWSTRIDE) + ks * 32);
            ldm_x4(bl, bLo + np * (16 * ROWSTRIDE) + ks * 32);
            float* c0 = c + 8 * np;
            float* c1 = c + 8 * np + 4;
            mma16816(c0, ahi, bh[0], bh[1]);
            mma16816(c1, ahi, bh[2], bh[3]);
            mma16816(c0, ahi, bl[0], bl[1]);
            mma16816(c1, ahi, bl[2], bl[3]);
            mma16816(c0, alo, bh[0], bh[1]);
            mma16816(c1, alo, bh[2], bh[3]);
        }
    }
}

__device__ __forceinline__ void cvt_sts(unsigned char* smem, uint32_t hiBase, uint32_t loBase,
                                        uint32_t off, float4 v) {
    __nv_bfloat162 h01 = __floats2bfloat162_rn(v.x, v.y);
    __nv_bfloat162 h23 = __floats2bfloat162_rn(v.z, v.w);
    __nv_bfloat162 l01 = __floats2bfloat162_rn(v.x - __low2float(h01), v.y - __high2float(h01));
    __nv_bfloat162 l23 = __floats2bfloat162_rn(v.z - __low2float(h23), v.w - __high2float(h23));
    *reinterpret_cast<uint2*>(smem + hiBase + off) =
        make_uint2(*reinterpret_cast<uint32_t*>(&h01), *reinterpret_cast<uint32_t*>(&h23));
    *reinterpret_cast<uint2*>(smem + loBase + off) =
        make_uint2(*reinterpret_cast<uint32_t*>(&l01), *reinterpret_cast<uint32_t*>(&l23));
}

__global__ void k_fill(float* __restrict__ p, float v, int n) {
    int i = blockIdx.x * blockDim.x + threadIdx.x;
    if (i < n) p[i] = v;
}

__global__ void k_ifill(int* __restrict__ p, int v, int n) {
    int i = blockIdx.x * blockDim.x + threadIdx.x;
    if (i < n) p[i] = v;
}

// ---------------- CSR build (hierarchical scan) ----------------
__global__ void k_hist(const int* __restrict__ ei) {
    int e = blockIdx.x * blockDim.x + threadIdx.x;
    if (e < Ee) atomicAdd(&g_wp[ei[Ee + e]], 1);
}

__global__ void k_scanA() {
    __shared__ int sh[256];
    int b = blockIdx.x, t = threadIdx.x;
    int i = b * 256 + t;
    int v = (i < Nn) ? g_wp[i] : 0;
    sh[t] = v;
    __syncthreads();
#pragma unroll
    for (int o = 1; o < 256; o <<= 1) {
        int u = (t >= o) ? sh[t - o] : 0;
        __syncthreads();
        sh[t] += u;
        __syncthreads();
    }
    if (i < Nn) g_rowptr[i] = sh[t] - v;
    if (t == 255) g_bsum[b] = sh[255];
}

__global__ void k_scanB(int nblk) {
    __shared__ int sh[256];
    int t = threadIdx.x;
    int v = (t < nblk) ? g_bsum[t] : 0;
    sh[t] = v;
    __syncthreads();
#pragma unroll
    for (int o = 1; o < 256; o <<= 1) {
        int u = (t >= o) ? sh[t - o] : 0;
        __syncthreads();
        sh[t] += u;
        __syncthreads();
    }
    if (t < nblk) g_bsum[t] = sh[t] - v;
}

__global__ void k_scanC() {
    int i = blockIdx.x * blockDim.x + threadIdx.x;
    if (i < Nn) {
        int v = g_rowptr[i] + g_bsum[i >> 8];
        g_rowptr[i] = v;
        g_wp[i] = v;
    }
    if (i == 0) g_rowptr[Nn] = Ee;
}

__global__ void k_place(const int* __restrict__ ei) {
    int e = blockIdx.x * blockDim.x + threadIdx.x;
    if (e >= Ee) return;
    int d = ei[Ee + e];
    int p = atomicAdd(&g_wp[d], 1);
    g_pos[e] = p;
    g_eid[p] = e;
    g_srcC[p] = ei[e];
}

// ---------------- loop_attr mean (CSR gather) ----------------
__global__ void k_loop_mean(const float* __restrict__ eattr) {
    int t = blockIdx.x * blockDim.x + threadIdx.x;
    int d = t >> 5, lane = t & 31;
    if (d >= Nn) return;
    int start = g_rowptr[d], end = g_rowptr[d + 1];
    float4 acc = make_float4(0.f, 0.f, 0.f, 0.f);
    for (int j = start; j < end; j++) {
        int eid = g_eid[j];
        float4 a = reinterpret_cast<const float4*>(eattr)[(size_t)eid * 32 + lane];
        acc.x += a.x; acc.y += a.y; acc.z += a.z; acc.w += a.w;
    }
    float inv = 1.f / (float)max(end - start, 1);
    reinterpret_cast<float4*>(g_loop)[(size_t)d * 32 + lane] =
        make_float4(acc.x * inv, acc.y * inv, acc.z * inv, acc.w * inv);
}

// ---------------- per-dst softmax + aggregation (4-way pipelined gather) ----------------
__global__ void k_node_agg() {
    int t = blockIdx.x * blockDim.x + threadIdx.x;
    int d = t >> 5, lane = t & 31;
    if (d >= Nn) return;
    int start = g_rowptr[d], end = g_rowptr[d + 1];

    float es = g_eself[d];
    float m = es;
    for (int j = start + lane; j < end; j += 32) m = fmaxf(m, g_ecsr[j]);
#pragma unroll
    for (int o = 16; o > 0; o >>= 1) m = fmaxf(m, __shfl_xor_sync(0xffffffffu, m, o));
    float s = (lane == 0) ? __expf(es - m) : 0.f;
    for (int j = start + lane; j < end; j += 32) s += __expf(g_ecsr[j] - m);
#pragma unroll
    for (int o = 16; o > 0; o >>= 1) s += __shfl_xor_sync(0xffffffffu, s, o);
    float inv = 1.f / s;
    float aS = __expf(es - m) * inv;
    float4 xv = reinterpret_cast<const float4*>(g_xl)[(size_t)d * 32 + lane];
    float4 acc = make_float4(aS * xv.x, aS * xv.y, aS * xv.z, aS * xv.w);

    const float4* xl4 = reinterpret_cast<const float4*>(g_xl);
    int j = start;
    // 4-way unrolled gather: independent row loads in flight (same accumulation order)
    for (; j + 4 <= end; j += 4) {
        float a0 = __expf(g_ecsr[j + 0] - m) * inv;
        float a1 = __expf(g_ecsr[j + 1] - m) * inv;
        float a2 = __expf(g_ecsr[j + 2] - m) * inv;
        float a3 = __expf(g_ecsr[j + 3] - m) * inv;
        int s0 = g_srcC[j + 0], s1 = g_srcC[j + 1], s2 = g_srcC[j + 2], s3 = g_srcC[j + 3];
        float4 v0 = xl4[(size_t)s0 * 32 + lane];
        float4 v1 = xl4[(size_t)s1 * 32 + lane];
        float4 v2 = xl4[(size_t)s2 * 32 + lane];
        float4 v3 = xl4[(size_t)s3 * 32 + lane];
        acc.x = fmaf(a0, v0.x, acc.x); acc.y = fmaf(a0, v0.y, acc.y);
        acc.z = fmaf(a0, v0.z, acc.z); acc.w = fmaf(a0, v0.w, acc.w);
        acc.x = fmaf(a1, v1.x, acc.x); acc.y = fmaf(a1, v1.y, acc.y);
        acc.z = fmaf(a1, v1.z, acc.z); acc.w = fmaf(a1, v1.w, acc.w);
        acc.x = fmaf(a2, v2.x, acc.x); acc.y = fmaf(a2, v2.y, acc.y);
        acc.z = fmaf(a2, v2.z, acc.z); acc.w = fmaf(a2, v2.w, acc.w);
        acc.x = fmaf(a3, v3.x, acc.x); acc.y = fmaf(a3, v3.y, acc.y);
        acc.z = fmaf(a3, v3.z, acc.z); acc.w = fmaf(a3, v3.w, acc.w);
    }
    for (; j < end; j++) {
        float a = __expf(g_ecsr[j] - m) * inv;
        int sn = g_srcC[j];
        float4 v = xl4[(size_t)sn * 32 + lane];
        acc.x = fmaf(a, v.x, acc.x); acc.y = fmaf(a, v.y, acc.y);
        acc.z = fmaf(a, v.z, acc.z); acc.w = fmaf(a, v.w, acc.w);
    }
    reinterpret_cast<float4*>(g_agg)[(size_t)d * 32 + lane] = acc;
}

// ---------------- weight pre-split ----------------
struct W9 { const float* p[9]; };

__global__ void k_prep_all(W9 w, unsigned char* __restrict__ bw) {
    int idx = blockIdx.x * blockDim.x + threadIdx.x;
    if (idx >= 9 * 16384) return;
    int mi = idx >> 14;
    int rem = idx & 16383;
    int n = rem >> 7;
    int k = rem & 127;
    const float* W = w.p[mi];
    unsigned char* blob = bw + (size_t)mi * BLOB_BYTES;
    float v = W[k * 128 + n];
    __nv_bfloat16 h = __float2bfloat16_rn(v);
    __nv_bfloat16 l = __float2bfloat16_rn(v - __bfloat162float(h));
    size_t off = ((size_t)n * 136 + k) * 2;
    *reinterpret_cast<unsigned short*>(blob + off) = *reinterpret_cast<unsigned short*>(&h);
    *reinterpret_cast<unsigned short*>(blob + 34816 + off) = *reinterpret_cast<unsigned short*>(&l);
}

#define SM_ATT 0
#define SM_RED 512
#define SM_A_HI 1024
#define SM_A_LO 35840
#define SM_B_HI 70656
#define SMEM_BYTES 140288

// ===================== persistent edge+self score GEMM =====================
__global__ void __launch_bounds__(512, 1)
k_edge_persist(const float* __restrict__ eattr, const unsigned char* __restrict__ Bblob,
               const float* __restrict__ att, const int* __restrict__ ei,
               const float* __restrict__ xl, const float* __restrict__ xr,
               int tilesE, int tilesT) {
    extern __shared__ unsigned char smem[];
    const int tid = threadIdx.x;
    const int wid = tid >> 5;
    const int lane = tid & 31;
    const int rowtile = wid & 7;
    const int colhalf = wid >> 3;
    uint32_t sb;
    asm("{ .reg .u64 t; cvta.to.shared.u64 t, %1; cvt.u32.u64 %0, t; }" : "=r"(sb) : "l"(smem));

#pragma unroll
    for (int i = 0; i < 9; i++) {
        int idx = tid + 512 * i;
        if (idx < 4352) CP_ASYNC16(sb + SM_B_HI + idx * 16, Bblob + (size_t)idx * 16);
    }
    CP_COMMIT();
    if (tid < 32)
        reinterpret_cast<float4*>(smem + SM_ATT)[tid] = reinterpret_cast<const float4*>(att)[tid];
    CP_WAIT0();
    __syncthreads();

    const float* att_s = reinterpret_cast<const float*>(smem + SM_ATT);
    float* sred = reinterpret_cast<float*>(smem + SM_RED);

    uint32_t a_off = (uint32_t)(rowtile * 16 + (lane & 7) + ((lane >> 3) & 1) * 8) * ROWSTRIDE
                     + ((lane >> 4) & 1) * 16;
    uint32_t b_off = (uint32_t)(colhalf * 64 + (lane & 7) + ((lane >> 4) & 1) * 8) * ROWSTRIDE
                     + ((lane >> 3) & 1) * 16;
    uint32_t aHi = sb + SM_A_HI + a_off;
    uint32_t aLo = sb + SM_A_LO + a_off;
    uint32_t bHi = sb + SM_B_HI + b_off;
    uint32_t bLo = bHi + 34816;
    const int q = lane & 3;

    for (int tile = blockIdx.x; tile < tilesT; tile += gridDim.x) {
        const bool selfmode = tile >= tilesE;
        const int row0 = (selfmode ? tile - tilesE : tile) * 128;
        const int limit = selfmode ? Nn : Ee;
        const float* Asrc = selfmode ? g_loop : eattr;

#pragma unroll
        for (int i = 0; i < 8; i++) {
            int idx = tid + 512 * i;
            int r = idx >> 5;
            int c4 = (idx & 31) << 2;
            int grow = row0 + r;
            float4 v = make_float4(0.f, 0.f, 0.f, 0.f);
            if (grow < limit)
                v = *reinterpret_cast<const float4*>(Asrc + (size_t)grow * Hh + c4);
            cvt_sts(smem, SM_A_HI, SM_A_LO, (uint32_t)r * ROWSTRIDE + c4 * 2, v);
        }
        __syncthreads();

        float c[32];
#pragma unroll
        for (int i = 0; i < 32; i++) c[i] = 0.f;

        mm16x64(c, aHi, aLo, bHi, bLo);

        const int r1 = row0 + rowtile * 16 + (lane >> 2);
        float accv[2];
        int rowv[2];
#pragma unroll
        for (int p = 0; p < 2; p++) {
            int row = r1 + 8 * p;
            rowv[p] = row;
            bool valid = row < limit;
            int s = 0, dd = 0;
            if (valid) {
                if (selfmode) { s = row; dd = row; }
                else { s = ei[row]; dd = ei[Ee + row]; }
            }
            const float* xlp = xl + (size_t)s * Hh;
            const float* xrp = xr + (size_t)dd * Hh;
            float acc = 0.f;
            if (valid) {
#pragma unroll
                for (int j = 0; j < 8; j++) {
                    int col = colhalf * 64 + j * 8 + q * 2;
                    int base = 8 * (j >> 1) + 4 * (j & 1) + 2 * p;
                    float2 xa = *reinterpret_cast<const float2*>(xlp + col);
                    float2 xb = *reinterpret_cast<const float2*>(xrp + col);
                    float2 at = *reinterpret_cast<const float2*>(att_s + col);
                    float m;
                    m = c[base + 0] + xa.x + xb.x;
                    m = m > 0.f ? m : 0.2f * m;
                    acc = fmaf(m, at.x, acc);
                    m = c[base + 1] + xa.y + xb.y;
                    m = m > 0.f ? m : 0.2f * m;
                    acc = fmaf(m, at.y, acc);
                }
            }
            acc += __shfl_xor_sync(0xffffffffu, acc, 1);
            acc += __shfl_xor_sync(0xffffffffu, acc, 2);
            accv[p] = acc;
        }
        int rl = rowtile * 16 + (lane >> 2);
        if (colhalf == 0 && q == 0) {
            sred[rl] = accv[0];
            sred[rl + 8] = accv[1];
        }
        __syncthreads();
        if (colhalf == 1 && q == 0) {
#pragma unroll
            for (int p = 0; p < 2; p++) {
                if (rowv[p] < limit) {
                    float e = accv[p] + sred[rl + 8 * p];
                    if (selfmode) g_eself[rowv[p]] = e;
                    else g_ecsr[g_pos[rowv[p]]] = e;
                }
            }
        }
        __syncthreads();
    }
}

// ===================== BM=128 GEMM, 512 threads (gate/final) =====================
// EPI: 0 store+bias, 1 tanh(+bias), 2 tanh(+bias)*PI
template <int EPI>
__global__ void __launch_bounds__(512, 1)
k_mma_gemm(const float* __restrict__ A, const unsigned char* __restrict__ Bblob,
           const float* __restrict__ bias, float* __restrict__ C, int rows) {
    extern __shared__ unsigned char smem[];
    const int tid = threadIdx.x;
    const int wid = tid >> 5;
    const int lane = tid & 31;
    const int rowtile = wid & 7;
    const int colhalf = wid >> 3;
    uint32_t sb;
    asm("{ .reg .u64 t; cvta.to.shared.u64 t, %1; cvt.u32.u64 %0, t; }" : "=r"(sb) : "l"(smem));

    const int row0 = blockIdx.x * 128;

#pragma unroll
    for (int i = 0; i < 9; i++) {
        int idx = tid + 512 * i;
        if (idx < 4352) CP_ASYNC16(sb + SM_B_HI + idx * 16, Bblob + (size_t)idx * 16);
    }
    CP_COMMIT();

#pragma unroll
    for (int i = 0; i < 8; i++) {
        int idx = tid + 512 * i;
        int r = idx >> 5;
        int c4 = (idx & 31) << 2;
        int grow = row0 + r;
        float4 v = make_float4(0.f, 0.f, 0.f, 0.f);
        if (grow < rows)
            v = *reinterpret_cast<const float4*>(A + (size_t)grow * Hh + c4);
        cvt_sts(smem, SM_A_HI, SM_A_LO, (uint32_t)r * ROWSTRIDE + c4 * 2, v);
    }
    CP_WAIT0();
    __syncthreads();

    float c[32];
#pragma unroll
    for (int i = 0; i < 32; i++) c[i] = 0.f;

    uint32_t a_off = (uint32_t)(rowtile * 16 + (lane & 7) + ((lane >> 3) & 1) * 8) * ROWSTRIDE
                     + ((lane >> 4) & 1) * 16;
    uint32_t b_off = (uint32_t)(colhalf * 64 + (lane & 7) + ((lane >> 4) & 1) * 8) * ROWSTRIDE
                     + ((lane >> 3) & 1) * 16;
    uint32_t aHi = sb + SM_A_HI + a_off;
    uint32_t aLo = sb + SM_A_LO + a_off;
    uint32_t bHi = sb + SM_B_HI + b_off;
    uint32_t bLo = bHi + 34816;

    mm16x64(c, aHi, aLo, bHi, bLo);

    const int q = lane & 3;
    const int r1 = row0 + rowtile * 16 + (lane >> 2);
    int r2 = r1 + 8;
#pragma unroll
    for (int j = 0; j < 8; j++) {
        int col = colhalf * 64 + j * 8 + q * 2;
        int base = 8 * (j >> 1) + 4 * (j & 1);
        float b0 = bias[col], b1 = bias[col + 1];
        if (r1 < rows) {
            float ox = c[base + 0] + b0;
            float oy = c[base + 1] + b1;
            if (EPI == 1) { ox = tanhf(ox); oy = tanhf(oy); }
            if (EPI == 2) { ox = tanhf(ox) * PI_F; oy = tanhf(oy) * PI_F; }
            *reinterpret_cast<float2*>(C + (size_t)r1 * Hh + col) = make_float2(ox, oy);
        }
        if (r2 < rows) {
            float ox = c[base + 2] + b0;
            float oy = c[base + 3] + b1;
            if (EPI == 1) { ox = tanhf(ox); oy = tanhf(oy); }
            if (EPI == 2) { ox = tanhf(ox) * PI_F; oy = tanhf(oy) * PI_F; }
            *reinterpret_cast<float2*>(C + (size_t)r2 * Hh + col) = make_float2(ox, oy);
        }
    }
}

// ===================== persistent dual-B BM=64 GEMM (B1+B2 resident) =====================
#define SD_A_HI 0
#define SD_A_LO 17408
#define SD_B 34816
#define SMEM_DUAL 174080

__global__ void __launch_bounds__(512, 1)
k_gemm_dual(const float* __restrict__ A,
            const unsigned char* __restrict__ B1, const unsigned char* __restrict__ B2,
            const float* __restrict__ bias1, const float* __restrict__ bias2,
            float* __restrict__ C1, float* __restrict__ C2, int rows, int tilesT) {
    extern __shared__ unsigned char smem[];
    const int tid = threadIdx.x;
    const int wid = tid >> 5;
    const int lane = tid & 31;
    const int rowtile = wid & 3;
    const int colhalf = (wid >> 2) & 1;
    const int outsel = wid >> 3;
    uint32_t sb;
    asm("{ .reg .u64 t; cvta.to.shared.u64 t, %1; cvt.u32.u64 %0, t; }" : "=r"(sb) : "l"(smem));

#pragma unroll
    for (int i = 0; i < 9; i++) {
        int idx = tid + 512 * i;
        if (idx < 4352) {
            CP_ASYNC16(sb + SD_B + idx * 16, B1 + (size_t)idx * 16);
            CP_ASYNC16(sb + SD_B + BLOB_BYTES + idx * 16, B2 + (size_t)idx * 16);
        }
    }
    CP_COMMIT();
    CP_WAIT0();
    __syncthreads();

    uint32_t a_off = (uint32_t)(rowtile * 16 + (lane & 7) + ((lane >> 3) & 1) * 8) * ROWSTRIDE
                     + ((lane >> 4) & 1) * 16;
    uint32_t b_off = (uint32_t)(colhalf * 64 + (lane & 7) + ((lane >> 4) & 1) * 8) * ROWSTRIDE
                     + ((lane >> 3) & 1) * 16;
    uint32_t aHi = sb + SD_A_HI + a_off;
    uint32_t aLo = sb + SD_A_LO + a_off;
    uint32_t bHi = sb + SD_B + outsel * BLOB_BYTES + b_off;
    uint32_t bLo = bHi + 34816;
    const int q = lane & 3;
    const float* bias = outsel ? bias2 : bias1;
    float* C = outsel ? C2 : C1;

    for (int tile = blockIdx.x; tile < tilesT; tile += gridDim.x) {
        const int row0 = tile * 64;
#pragma unroll
        for (int i = 0; i < 4; i++) {
            int idx = tid + 512 * i;
            int r = idx >> 5;
            int c4 = (idx & 31) << 2;
            int grow = row0 + r;
            float4 v = make_float4(0.f, 0.f, 0.f, 0.f);
            if (grow < rows)
                v = *reinterpret_cast<const float4*>(A + (size_t)grow * Hh + c4);
            cvt_sts(smem, SD_A_HI, SD_A_LO, (uint32_t)r * ROWSTRIDE + c4 * 2, v);
        }
        __syncthreads();

        float c[32];
#pragma unroll
        for (int i = 0; i < 32; i++) c[i] = 0.f;

        mm16x64(c, aHi, aLo, bHi, bLo);

        const int r1 = row0 + rowtile * 16 + (lane >> 2);
        const int r2 = r1 + 8;
#pragma unroll
        for (int j = 0; j < 8; j++) {
            int col = colhalf * 64 + j * 8 + q * 2;
            int base = 8 * (j >> 1) + 4 * (j & 1);
            float b0 = bias[col], b1 = bias[col + 1];
            if (r1 < rows)
                *reinterpret_cast<float2*>(C + (size_t)r1 * Hh + col) =
                    make_float2(c[base + 0] + b0, c[base + 1] + b1);
            if (r2 < rows)
                *reinterpret_cast<float2*>(C + (size_t)r2 * Hh + col) =
                    make_float2(c[base + 2] + b0, c[base + 3] + b1);
        }
        __syncthreads();
    }
}

// ---------------- batchnorm + tanh ----------------
__global__ void k_bn_stats(const float* __restrict__ cb) {
    int j = threadIdx.x;
    int r0 = blockIdx.x * 128;
    int r1 = min(r0 + 128, Nn);
    float cbj = cb[j];
    float s = 0.f, q = 0.f;
    for (int r = r0; r < r1; r++) {
        float v = g_agg[(size_t)r * Hh + j] + cbj;
        s += v; q += v * v;
    }
    atomicAdd(&g_bnsum[j], s);
    atomicAdd(&g_bnsq[j], q);
}

__global__ void k_bn_final() {
    int j = threadIdx.x;
    float mu = g_bnsum[j] / (float)Nn;
    float var = g_bnsq[j] / (float)Nn - mu * mu;
    g_mu[j] = mu;
    g_inv[j] = rsqrtf(var + 1e-5f);
    g_bnsum[j] = 0.f;
    g_bnsq[j] = 0.f;
}

__global__ void k_bn_apply(const float* __restrict__ cb, const float* __restrict__ gam,
                           const float* __restrict__ bet) {
    int i = blockIdx.x * blockDim.x + threadIdx.x;
    if (i >= Nn * Hh) return;
    int j = i & 127;
    float v = g_agg[i] + cb[j];
    v = (v - g_mu[j]) * g_inv[j] * gam[j] + bet[j];
    g_h[i] = tanhf(v);
}

// ---------------- pooling over sorted batch segments ----------------
__global__ void k_gb_min(const int* __restrict__ batch) {
    int n = blockIdx.x * blockDim.x + threadIdx.x;
    if (n < Nn) atomicMin(&g_gstart[batch[n]], n);
}

__global__ void k_gb_fix() {
    __shared__ int sh[Gg];
    int t = threadIdx.x;
    sh[t] = g_gstart[t];
    __syncthreads();
#pragma unroll
    for (int o = 1; o < Gg; o <<= 1) {
        int u = (t + o < Gg) ? sh[t + o] : Nn;
        __syncthreads();
        sh[t] = min(sh[t], u);
        __syncthreads();
    }
    g_gstart[t] = sh[t];
    if (t == 0) g_gstart[Gg] = Nn;
}

__global__ void k_pool() {
    int g = blockIdx.x;
    int j = threadIdx.x;
    int s = g_gstart[g], e2 = g_gstart[g + 1];
    float m = -FLT_MAX;
    for (int n = s; n < e2; n++) m = fmaxf(m, g_gate[(size_t)n * Hh + j]);
    float den = 0.f, num = 0.f;
    for (int n = s; n < e2; n++) {
        float ex = __expf(g_gate[(size_t)n * Hh + j] - m);
        den += ex;
        num = fmaf(ex, g_h[(size_t)n * Hh + j], num);
    }
    g_pooled[g * Hh + j] = num / fmaxf(den, 1e-16f);
}

// ---------------- launch ----------------
static inline int cdiv(long a, long b) { return (int)((a + b - 1) / b); }

extern "C" void kernel_launch(void* const* d_in, const int* in_sizes, int n_in,
                              void* d_out, int out_size) {
    const float* x     = (const float*)d_in[0];
    const int*   ei    = (const int*)d_in[1];
    const float* eattr = (const float*)d_in[2];
    const int*   batch = (const int*)d_in[3];
    const float* Wl[2]  = {(const float*)d_in[4],  (const float*)d_in[11]};
    const float* bl[2]  = {(const float*)d_in[5],  (const float*)d_in[12]};
    const float* Wr[2]  = {(const float*)d_in[6],  (const float*)d_in[13]};
    const float* br[2]  = {(const float*)d_in[7],  (const float*)d_in[14]};
    const float* We[2]  = {(const float*)d_in[8],  (const float*)d_in[15]};
    const float* att[2] = {(const float*)d_in[9],  (const float*)d_in[16]};
    const float* cb[2]  = {(const float*)d_in[10], (const float*)d_in[17]};
    const float* gm[2]  = {(const float*)d_in[18], (const float*)d_in[20]};
    const float* bt[2]  = {(const float*)d_in[19], (const float*)d_in[21]};
    const float* A1 = (const float*)d_in[22]; const float* a1 = (const float*)d_in[23];
    const float* A2 = (const float*)d_in[24]; const float* a2 = (const float*)d_in[25];
    const float* Wf = (const float*)d_in[26]; const float* bf = (const float*)d_in[27];
    float* out = (float*)d_out;

    float *p_xl, *p_xr, *p_h, *p_gate, *p_tmp, *p_pooled;
    int *p_wp, *p_gstart;
    unsigned char* p_bw;
    cudaGetSymbolAddress((void**)&p_xl, g_xl);
    cudaGetSymbolAddress((void**)&p_xr, g_xr);
    cudaGetSymbolAddress((void**)&p_h, g_h);
    cudaGetSymbolAddress((void**)&p_gate, g_gate);
    cudaGetSymbolAddress((void**)&p_tmp, g_tmp);
    cudaGetSymbolAddress((void**)&p_pooled, g_pooled);
    cudaGetSymbolAddress((void**)&p_wp, g_wp);
    cudaGetSymbolAddress((void**)&p_gstart, g_gstart);
    cudaGetSymbolAddress((void**)&p_bw, g_bw);

    cudaFuncSetAttribute(k_mma_gemm<0>, cudaFuncAttributeMaxDynamicSharedMemorySize, SMEM_BYTES);
    cudaFuncSetAttribute(k_mma_gemm<1>, cudaFuncAttributeMaxDynamicSharedMemorySize, SMEM_BYTES);
    cudaFuncSetAttribute(k_mma_gemm<2>, cudaFuncAttributeMaxDynamicSharedMemorySize, SMEM_BYTES);
    cudaFuncSetAttribute(k_edge_persist, cudaFuncAttributeMaxDynamicSharedMemorySize, SMEM_BYTES);
    cudaFuncSetAttribute(k_gemm_dual, cudaFuncAttributeMaxDynamicSharedMemorySize, SMEM_DUAL);

    const int NH = Nn * Hh;
    const int tilesN = cdiv(Nn, 128), tilesE = cdiv(Ee, 128), tilesG = cdiv(Gg, 128);
    const int t64N = cdiv(Nn, 64);
    const int nScanBlk = cdiv(Nn, 256);

    // 0: weight blobs (order: Wl1,Wr1,We1,Wl2,Wr2,We2,A1,A2,Wf)
    W9 w9;
    w9.p[0] = Wl[0]; w9.p[1] = Wr[0]; w9.p[2] = We[0];
    w9.p[3] = Wl[1]; w9.p[4] = Wr[1]; w9.p[5] = We[1];
    w9.p[6] = A1; w9.p[7] = A2; w9.p[8] = Wf;
    k_prep_all<<<cdiv(9 * 16384, 512), 512>>>(w9, p_bw);

    // 1-2: CSR histogram
    k_ifill<<<cdiv(Nn, 256), 256>>>(p_wp, 0, Nn);
    k_hist<<<cdiv(Ee, 256), 256>>>(ei);

    // 3: layer-1 xl/xr persistent dual GEMM (ncu capture slot)
    k_gemm_dual<<<148, 512, SMEM_DUAL>>>(x, p_bw, p_bw + BLOB_BYTES, bl[0], br[0],
                                         p_xl, p_xr, Nn, t64N);

    // CSR scan + placement
    k_scanA<<<nScanBlk, 256>>>();
    k_scanB<<<1, 256>>>(nScanBlk);
    k_scanC<<<cdiv(Nn, 256), 256>>>();
    k_place<<<cdiv(Ee, 256), 256>>>(ei);

    // graph segment bounds + loop_attr mean
    k_ifill<<<cdiv(Gg + 1, 256), 256>>>(p_gstart, Nn, Gg + 1);
    k_gb_min<<<cdiv(Nn, 256), 256>>>(batch);
    k_gb_fix<<<1, Gg>>>();
    k_loop_mean<<<cdiv((long)Nn * 32, 256), 256>>>(eattr);

    for (int l = 0; l < 2; l++) {
        const unsigned char* bwe = p_bw + (size_t)(3 * l + 2) * BLOB_BYTES;
        if (l == 1) {
            k_gemm_dual<<<148, 512, SMEM_DUAL>>>(p_h, p_bw + 3ul * BLOB_BYTES,
                                                 p_bw + 4ul * BLOB_BYTES, bl[1], br[1],
                                                 p_xl, p_xr, Nn, t64N);
        }
        // persistent fused edge+self score GEMM
        k_edge_persist<<<148, 512, SMEM_BYTES>>>(eattr, bwe, att[l], ei,
                                                 p_xl, p_xr, tilesE, tilesE + tilesN);
        k_node_agg<<<cdiv((long)Nn * 32, 256), 256>>>();

        k_bn_stats<<<cdiv(Nn, 128), 128>>>(cb[l]);
        k_bn_final<<<1, 128>>>();
        k_bn_apply<<<cdiv(NH, 256), 256>>>(cb[l], gm[l], bt[l]);
    }

    // gate = tanh(h@A1+a1)@A2 + a2
    k_mma_gemm<1><<<tilesN, 512, SMEM_BYTES>>>(p_h, p_bw + 6ul * BLOB_BYTES, a1, p_tmp, Nn);
    k_mma_gemm<0><<<tilesN, 512, SMEM_BYTES>>>(p_tmp, p_bw + 7ul * BLOB_BYTES, a2, p_gate, Nn);
    k_pool<<<Gg, 128>>>();

    // final linear + tanh*pi -> axis; aperture = zeros
    k_mma_gemm<2><<<tilesG, 512, SMEM_BYTES>>>(p_pooled, p_bw + 8ul * BLOB_BYTES, bf, out, Gg);
    int rem = out_size - Gg * Hh;
    if (rem > 0) k_fill<<<cdiv(rem, 256), 256>>>(out + Gg * Hh, 0.f, rem);
}